// round 9
// baseline (speedup 1.0000x reference)
#include <cuda_runtime.h>
#include <cuda_bf16.h>
#include <math.h>
#include <stdint.h>

#define B_      16384
#define K_      32
#define LATENT_ 256
#define ACT_    64
#define H_      128
#define Q_      65536
#define EPS_    0.01f
#define PGRID   148
#define NSTREAM (PGRID * 2)

// ---------------- scratch (device globals; no runtime alloc) ----------------
__device__ __nv_bfloat16 g_emb_a[B_ * H_];
__device__ __nv_bfloat16 g_emb_l[B_ * H_];
__device__ __nv_bfloat16 g_negemb[Q_ * H_];
__device__ __nv_bfloat16 g_aw1t[H_ * ACT_];     // [H][ACT]    = a_w1^T
__device__ __nv_bfloat16 g_aw2t[H_ * H_];       // [H][H]      = a_w2^T
__device__ __nv_bfloat16 g_lw1t[H_ * LATENT_];  // [H][LATENT] = l_w1^T
__device__ __nv_bfloat16 g_lw2t[H_ * H_];       // [H][H]      = l_w2^T

__device__ __forceinline__ float san(float x) { return isfinite(x) ? x : 0.0f; }

__device__ __forceinline__ uint32_t smem_u32(const void* p) {
    uint32_t a;
    asm("{ .reg .u64 t; cvta.to.shared.u64 t, %1; cvt.u32.u64 %0, t; }" : "=r"(a) : "l"(p));
    return a;
}
__device__ __forceinline__ uint32_t pack_bf16x2(float lo, float hi) {
    uint32_t r;
    asm("cvt.rn.bf16x2.f32 %0, %1, %2;" : "=r"(r) : "f"(hi), "f"(lo));
    return r;
}
__device__ __forceinline__ void ldsm4(uint32_t* r, uint32_t addr) {
    asm volatile("ldmatrix.sync.aligned.m8n8.x4.shared.b16 {%0,%1,%2,%3}, [%4];"
                 : "=r"(r[0]), "=r"(r[1]), "=r"(r[2]), "=r"(r[3]) : "r"(addr));
}
__device__ __forceinline__ void mma16816(float* d, const uint32_t* a, const uint32_t* b) {
    asm volatile(
        "mma.sync.aligned.m16n8k16.row.col.f32.bf16.bf16.f32 "
        "{%0,%1,%2,%3}, {%4,%5,%6,%7}, {%8,%9}, {%0,%1,%2,%3};"
        : "+f"(d[0]), "+f"(d[1]), "+f"(d[2]), "+f"(d[3])
        : "r"(a[0]), "r"(a[1]), "r"(a[2]), "r"(a[3]), "r"(b[0]), "r"(b[1]));
}
__device__ __forceinline__ void cp_async16(uint32_t dst, const void* src) {
    asm volatile("cp.async.cg.shared.global [%0], [%1], 16;" :: "r"(dst), "l"(src));
}
#define CP_COMMIT() asm volatile("cp.async.commit_group;" ::: "memory")
#define CP_WAIT0()  asm volatile("cp.async.wait_group 0;" ::: "memory")

// team-local barrier: team 0 -> id 1, team 1 -> id 2 (id 0 is __syncthreads)
__device__ __forceinline__ void team_bar(int team) {
    asm volatile("bar.sync %0, 256;" :: "r"(team + 1) : "memory");
}

// ---------------------------------------------------------------------------
// Tiled transpose + bf16 convert: out[n][k] = bf16(in[k][n]).
// ---------------------------------------------------------------------------
__global__ __launch_bounds__(256) void prep_weights(
    const float* __restrict__ aw1, const float* __restrict__ aw2,
    const float* __restrict__ lw1, const float* __restrict__ lw2)
{
    __shared__ float ts[32][33];
    int bid = blockIdx.x;
    const float* in;
    __nv_bfloat16* out;
    int rows, cols, t;
    if (bid < 8)        { in = aw1; out = g_aw1t; rows = 64;  cols = 128; t = bid; }
    else if (bid < 24)  { in = aw2; out = g_aw2t; rows = 128; cols = 128; t = bid - 8; }
    else if (bid < 56)  { in = lw1; out = g_lw1t; rows = 256; cols = 128; t = bid - 24; }
    else                { in = lw2; out = g_lw2t; rows = 128; cols = 128; t = bid - 56; }

    int tilesPerRow = cols / 32;
    int r0 = (t / tilesPerRow) * 32;
    int c0 = (t % tilesPerRow) * 32;
    int tx = threadIdx.x & 31, ty = threadIdx.x >> 5;

#pragma unroll
    for (int i = 0; i < 4; i++)
        ts[ty + i * 8][tx] = in[(size_t)(r0 + ty + i * 8) * cols + c0 + tx];
    __syncthreads();
#pragma unroll
    for (int i = 0; i < 4; i++) {
        int n = ty + i * 8;
        out[(size_t)(c0 + n) * rows + r0 + tx] = __float2bfloat16(ts[tx][n]);
    }
}

// ---------------------------------------------------------------------------
// Persistent fused MLP, 512 threads = 2 teams of 8 warps sharing weights.
// smem layout (sized for KIN=256):
//   [0,      67584)   W1T  [128][264] bf16            (shared)
//   [67584, 102400)   W2T  [128][136] bf16            (shared)
//   [102400,169984)   rx[2]  X tile [64][264] bf16    (per team, 33792 each)
//   [169984,204800)   rh[2]  hidden/out [64][136] bf16 (per team, 17408 each)
//   [204800,205824)   biases (2x128 fp32)
// ---------------------------------------------------------------------------
#define OFF_W2 67584
#define OFF_RX 102400
#define OFF_RH 169984
#define OFF_B  204800
#define SMEM_TOTAL 205824

template <int KIN>
__device__ void persist_phase(
    const float* __restrict__ X0, const float* __restrict__ X1, int split, int nTiles,
    const __nv_bfloat16* __restrict__ w1t, const __nv_bfloat16* __restrict__ w2t,
    const float* __restrict__ b1g, const float* __restrict__ b2g,
    __nv_bfloat16* __restrict__ out0, __nv_bfloat16* __restrict__ out1, char* smem)
{
    constexpr int S1 = KIN + 8;
    constexpr int SH = H_ + 8;
    constexpr int XV = 64 * KIN / 4 / 256;      // float4 per team-thread per X tile

    const int tid  = threadIdx.x;               // 0..511
    const int team = tid >> 8;                  // 0/1
    const int ltid = tid & 255;                 // team-local
    const int wid  = ltid >> 5;
    const int lane = ltid & 31;
    const int wr0 = (wid >> 2) * 32;
    const int wc0 = (wid & 3) * 32;
    const int a_row = (lane & 7) + ((lane >> 3) & 1) * 8;
    const int a_k   = (lane >> 4) * 8;
    const int b_n   = (lane & 7) + ((lane >> 4) & 1) * 8;
    const int b_k   = ((lane >> 3) & 1) * 8;
    const int tr = lane >> 2, tc = (lane & 3) * 2;

    char* rw1 = smem;
    char* rw2 = smem + OFF_W2;
    char* rx  = smem + OFF_RX + team * 33792;
    char* rh  = smem + OFF_RH + team * 17408;
    float* b1s = (float*)(smem + OFF_B);
    float* b2s = b1s + 128;
    const uint32_t sw1 = smem_u32(rw1);
    const uint32_t sw2 = smem_u32(rw2);
    const uint32_t sx  = smem_u32(rx);
    const uint32_t sh  = smem_u32(rh);

    // ---- prologue: stage weights (all 512 threads) ----
    if (tid < 128) { b1s[tid] = b1g[tid]; b2s[tid] = b2g[tid]; }
    {
        constexpr int NC = 128 * KIN / 8 / 512;
#pragma unroll
        for (int p = 0; p < NC; p++) {
            int idx = tid + p * 512;
            int r = idx / (KIN / 8), c = (idx % (KIN / 8)) * 8;
            cp_async16(sw1 + (uint32_t)(r * S1 + c) * 2, w1t + r * KIN + c);
        }
#pragma unroll
        for (int p = 0; p < 4; p++) {
            int idx = tid + p * 512;
            int r = idx >> 4, c = (idx & 15) * 8;
            cp_async16(sw2 + (uint32_t)(r * SH + c) * 2, w2t + r * H_ + c);
        }
        CP_COMMIT();
    }
    CP_WAIT0();
    __syncthreads();

    // ---- per-team persistent tile loop ----
    const int s0 = blockIdx.x * 2 + team;
    for (int t = s0; t < nTiles; t += NSTREAM) {
        const float* Xp = (t < split) ? X0 + (size_t)t * 64 * KIN
                                      : X1 + (size_t)(t - split) * 64 * KIN;
        __nv_bfloat16* out = (t < split) ? out0 + (size_t)t * 64 * H_
                                         : out1 + (size_t)(t - split) * 64 * H_;

        // ---- load X -> rx (batches of 4 float4: MLP=4, bounded regs) ----
#pragma unroll
        for (int p0 = 0; p0 < XV; p0 += 4) {
            float4 v[4];
#pragma unroll
            for (int j = 0; j < 4; j++) {
                int idx = ltid + (p0 + j) * 256;
                int r = idx / (KIN / 4), c = (idx % (KIN / 4)) * 4;
                v[j] = *(const float4*)(Xp + (size_t)r * KIN + c);
            }
#pragma unroll
            for (int j = 0; j < 4; j++) {
                int idx = ltid + (p0 + j) * 256;
                int r = idx / (KIN / 4), c = (idx % (KIN / 4)) * 4;
                uint2 u;
                u.x = pack_bf16x2(san(v[j].x), san(v[j].y));
                u.y = pack_bf16x2(san(v[j].z), san(v[j].w));
                *(uint2*)(rx + (r * S1 + c) * 2) = u;
            }
        }
        team_bar(team);

        float acc[2][4][4];
#pragma unroll
        for (int mi = 0; mi < 2; mi++)
#pragma unroll
            for (int ni = 0; ni < 4; ni++)
#pragma unroll
                for (int q = 0; q < 4; q++) acc[mi][ni][q] = 0.0f;

        // ---- layer 1 mma: A = rx, B = rw1 ----
        {
            uint32_t aaddr[2], baddr[2];
#pragma unroll
            for (int mi = 0; mi < 2; mi++)
                aaddr[mi] = sx + (uint32_t)((wr0 + mi * 16 + a_row) * S1 + a_k) * 2;
#pragma unroll
            for (int bi = 0; bi < 2; bi++)
                baddr[bi] = sw1 + (uint32_t)((wc0 + bi * 16 + b_n) * S1 + b_k) * 2;
#pragma unroll
            for (int ks = 0; ks < KIN / 16; ks++) {
                uint32_t a[2][4], b[4][2];
#pragma unroll
                for (int mi = 0; mi < 2; mi++) ldsm4(a[mi], aaddr[mi] + ks * 32);
#pragma unroll
                for (int bi = 0; bi < 2; bi++) {
                    uint32_t tq[4];
                    ldsm4(tq, baddr[bi] + ks * 32);
                    b[bi * 2][0] = tq[0]; b[bi * 2][1] = tq[1];
                    b[bi * 2 + 1][0] = tq[2]; b[bi * 2 + 1][1] = tq[3];
                }
#pragma unroll
                for (int mi = 0; mi < 2; mi++)
#pragma unroll
                    for (int ni = 0; ni < 4; ni++) mma16816(acc[mi][ni], a[mi], b[ni]);
            }
        }
        team_bar(team);                 // rx consumed

        // ---- epilogue 1: hidden = relu(acc + b1) -> rh ----
#pragma unroll
        for (int mi = 0; mi < 2; mi++)
#pragma unroll
            for (int ni = 0; ni < 4; ni++) {
                int col = wc0 + ni * 8 + tc;
                float bb0 = b1s[col], bb1 = b1s[col + 1];
                int row0 = wr0 + mi * 16 + tr;
                *(uint32_t*)(rh + (row0 * SH + col) * 2) =
                    pack_bf16x2(fmaxf(acc[mi][ni][0] + bb0, 0.0f),
                                fmaxf(acc[mi][ni][1] + bb1, 0.0f));
                *(uint32_t*)(rh + ((row0 + 8) * SH + col) * 2) =
                    pack_bf16x2(fmaxf(acc[mi][ni][2] + bb0, 0.0f),
                                fmaxf(acc[mi][ni][3] + bb1, 0.0f));
            }
        team_bar(team);                 // rh ready

        // ---- layer 2 mma: A = rh, B = rw2 ----
#pragma unroll
        for (int mi = 0; mi < 2; mi++)
#pragma unroll
            for (int ni = 0; ni < 4; ni++)
#pragma unroll
                for (int q = 0; q < 4; q++) acc[mi][ni][q] = 0.0f;
        {
            uint32_t aaddr[2], baddr[2];
#pragma unroll
            for (int mi = 0; mi < 2; mi++)
                aaddr[mi] = sh + (uint32_t)((wr0 + mi * 16 + a_row) * SH + a_k) * 2;
#pragma unroll
            for (int bi = 0; bi < 2; bi++)
                baddr[bi] = sw2 + (uint32_t)((wc0 + bi * 16 + b_n) * SH + b_k) * 2;
#pragma unroll
            for (int ks = 0; ks < H_ / 16; ks++) {
                uint32_t a[2][4], b[4][2];
#pragma unroll
                for (int mi = 0; mi < 2; mi++) ldsm4(a[mi], aaddr[mi] + ks * 32);
#pragma unroll
                for (int bi = 0; bi < 2; bi++) {
                    uint32_t tq[4];
                    ldsm4(tq, baddr[bi] + ks * 32);
                    b[bi * 2][0] = tq[0]; b[bi * 2][1] = tq[1];
                    b[bi * 2 + 1][0] = tq[2]; b[bi * 2 + 1][1] = tq[3];
                }
#pragma unroll
                for (int mi = 0; mi < 2; mi++)
#pragma unroll
                    for (int ni = 0; ni < 4; ni++) mma16816(acc[mi][ni], a[mi], b[ni]);
            }
        }
        team_bar(team);                 // rh consumed

        // ---- epilogue 2: san(acc + b2) -> rh stage ----
#pragma unroll
        for (int mi = 0; mi < 2; mi++)
#pragma unroll
            for (int ni = 0; ni < 4; ni++) {
                int col = wc0 + ni * 8 + tc;
                float bb0 = b2s[col], bb1 = b2s[col + 1];
                int row0 = wr0 + mi * 16 + tr;
                *(uint32_t*)(rh + (row0 * SH + col) * 2) =
                    pack_bf16x2(san(acc[mi][ni][0] + bb0), san(acc[mi][ni][1] + bb1));
                *(uint32_t*)(rh + ((row0 + 8) * SH + col) * 2) =
                    pack_bf16x2(san(acc[mi][ni][2] + bb0), san(acc[mi][ni][3] + bb1));
            }
        team_bar(team);                 // rh staged

        // ---- coalesced store ----
        {
            uint4* dst = (uint4*)out;
            const uint4* src = (const uint4*)rh;
            for (int i = ltid; i < 1024; i += 256) {
                int r = i >> 4, c = i & 15;
                dst[i] = src[r * (SH / 8) + c];
            }
        }
        // next iter: load X writes rx (disjoint from rh); the bar after it
        // orders this store's rh reads before next epilogue-1 rh writes.
    }
}

__global__ __launch_bounds__(512, 1) void persist_mlp(
    const float* __restrict__ action, const float* __restrict__ latent,
    const float* __restrict__ queue,
    const float* __restrict__ ab1, const float* __restrict__ ab2,
    const float* __restrict__ lb1, const float* __restrict__ lb2)
{
    extern __shared__ __align__(16) char smem[];
    // phase 1: queue (1024 tiles) + latent (256 tiles), KIN=256
    persist_phase<LATENT_>(queue, latent, 1024, 1280, g_lw1t, g_lw2t, lb1, lb2,
                           g_negemb, g_emb_l, smem);
    __syncthreads();
    // phase 2: action (256 tiles), KIN=64
    persist_phase<ACT_>(action, action, 256, 256, g_aw1t, g_aw2t, ab1, ab2,
                        g_emb_a, g_emb_a, smem);
}

// ---------------------------------------------------------------------------
// Loss (proven Round-5 version): one warp per sample, coalesced row gathers.
// ---------------------------------------------------------------------------
__device__ __forceinline__ float2 bf2(uint32_t u) {
    return __bfloat1622float2(*reinterpret_cast<__nv_bfloat162*>(&u));
}

__global__ __launch_bounds__(256) void loss_kernel(
    const int* __restrict__ neg_idx,
    const float* __restrict__ temp_ptr,
    float* __restrict__ out)
{
    const int warp = threadIdx.x >> 5;
    const int lane = threadIdx.x & 31;
    const int b = blockIdx.x * 8 + warp;

    float t = *temp_ptr;
    if (!isfinite(t)) t = 0.1f;
    t = fminf(fmaxf(t, 0.01f), 10.0f);
    const float invt = 1.0f / t;

    uint2 au = *(const uint2*)(g_emb_a + (size_t)b * H_ + lane * 4);
    float2 a01 = bf2(au.x), a23 = bf2(au.y);
    const int my_idx = neg_idx[b * K_ + lane];

    uint2 lu = *(const uint2*)(g_emb_l + (size_t)b * H_ + lane * 4);
    float2 l01 = bf2(lu.x), l23 = bf2(lu.y);
    float s = a01.x * l01.x + a01.y * l01.y + a23.x * l23.x + a23.y * l23.y;
#pragma unroll
    for (int o = 16; o > 0; o >>= 1) s += __shfl_xor_sync(0xffffffffu, s, o);
    float pos = s;

    float myneg = 0.0f;
    for (int k = 0; k < K_; k++) {
        int row = __shfl_sync(0xffffffffu, my_idx, k);
        uint2 nu = *(const uint2*)(g_negemb + (size_t)row * H_ + lane * 4);
        float2 n01 = bf2(nu.x), n23 = bf2(nu.y);
        float d = a01.x * n01.x + a01.y * n01.y + a23.x * n23.x + a23.y * n23.y;
#pragma unroll
        for (int o = 16; o > 0; o >>= 1) d += __shfl_xor_sync(0xffffffffu, d, o);
        if (lane == k) myneg = d;
    }

    pos *= invt;
    if (!isfinite(pos)) pos = 0.0f;
    pos = fminf(fmaxf(pos, -20.0f), 20.0f);
    myneg *= invt;
    if (!isfinite(myneg)) myneg = 0.0f;
    myneg = fminf(fmaxf(myneg, -20.0f), 20.0f);

    float m = myneg;
#pragma unroll
    for (int o = 16; o > 0; o >>= 1) m = fmaxf(m, __shfl_xor_sync(0xffffffffu, m, o));
    m = fmaxf(m, pos);

    float se = expf(myneg - m);
    float sl = myneg;
#pragma unroll
    for (int o = 16; o > 0; o >>= 1) {
        se += __shfl_xor_sync(0xffffffffu, se, o);
        sl += __shfl_xor_sync(0xffffffffu, sl, o);
    }
    se += expf(pos - m);
    sl += pos;

    float lse = m + logf(se);
    float logp0 = pos - lse;
    float meanlogp = sl * (1.0f / 33.0f) - lse;

    float loss = -(1.0f - EPS_) * logp0 - EPS_ * meanlogp;
    if (!isfinite(loss)) loss = 0.0f;
    loss = fminf(fmaxf(loss, -10.0f), 10.0f);

    if (lane == 0) out[b] = -loss;
}

// ---------------------------------------------------------------------------
extern "C" void kernel_launch(void* const* d_in, const int* in_sizes, int n_in,
                              void* d_out, int out_size)
{
    const float* action  = (const float*)d_in[0];
    const float* latent  = (const float*)d_in[1];
    const float* queue   = (const float*)d_in[2];
    const int*   neg_idx = (const int*)  d_in[3];
    const float* a_w1 = (const float*)d_in[4];
    const float* a_b1 = (const float*)d_in[5];
    const float* a_w2 = (const float*)d_in[6];
    const float* a_b2 = (const float*)d_in[7];
    const float* l_w1 = (const float*)d_in[8];
    const float* l_b1 = (const float*)d_in[9];
    const float* l_w2 = (const float*)d_in[10];
    const float* l_b2 = (const float*)d_in[11];
    const float* temp = (const float*)d_in[12];
    float* out = (float*)d_out;

    cudaFuncSetAttribute((const void*)persist_mlp,
                         cudaFuncAttributeMaxDynamicSharedMemorySize, SMEM_TOTAL);

    prep_weights<<<72, 256>>>(a_w1, a_w2, l_w1, l_w2);

    persist_mlp<<<PGRID, 512, SMEM_TOTAL>>>(action, latent, queue,
                                            a_b1, a_b2, l_b1, l_b2);

    loss_kernel<<<B_ / 8, 256>>>(neg_idx, temp, out);
}

// round 11
// speedup vs baseline: 1.0971x; 1.0971x over previous
#include <cuda_runtime.h>
#include <cuda_bf16.h>
#include <math.h>
#include <stdint.h>

#define B_      16384
#define K_      32
#define LATENT_ 256
#define ACT_    64
#define H_      128
#define Q_      65536
#define EPS_    0.01f
#define PGRID   148

// ---------------- scratch (device globals; no runtime alloc) ----------------
__device__ __nv_bfloat16 g_emb_a[B_ * H_];
__device__ __nv_bfloat16 g_emb_l[B_ * H_];
__device__ __nv_bfloat16 g_negemb[Q_ * H_];
__device__ __nv_bfloat16 g_aw1t[H_ * ACT_];     // [H][ACT]    = a_w1^T
__device__ __nv_bfloat16 g_aw2t[H_ * H_];       // [H][H]      = a_w2^T
__device__ __nv_bfloat16 g_lw1t[H_ * LATENT_];  // [H][LATENT] = l_w1^T
__device__ __nv_bfloat16 g_lw2t[H_ * H_];       // [H][H]      = l_w2^T

__device__ __forceinline__ float san(float x) { return isfinite(x) ? x : 0.0f; }

__device__ __forceinline__ uint32_t smem_u32(const void* p) {
    uint32_t a;
    asm("{ .reg .u64 t; cvta.to.shared.u64 t, %1; cvt.u32.u64 %0, t; }" : "=r"(a) : "l"(p));
    return a;
}
__device__ __forceinline__ uint32_t pack_bf16x2(float lo, float hi) {
    uint32_t r;
    asm("cvt.rn.bf16x2.f32 %0, %1, %2;" : "=r"(r) : "f"(hi), "f"(lo));
    return r;
}
__device__ __forceinline__ void ldsm4(uint32_t* r, uint32_t addr) {
    asm volatile("ldmatrix.sync.aligned.m8n8.x4.shared.b16 {%0,%1,%2,%3}, [%4];"
                 : "=r"(r[0]), "=r"(r[1]), "=r"(r[2]), "=r"(r[3]) : "r"(addr));
}
__device__ __forceinline__ void mma16816(float* d, const uint32_t* a, const uint32_t* b) {
    asm volatile(
        "mma.sync.aligned.m16n8k16.row.col.f32.bf16.bf16.f32 "
        "{%0,%1,%2,%3}, {%4,%5,%6,%7}, {%8,%9}, {%0,%1,%2,%3};"
        : "+f"(d[0]), "+f"(d[1]), "+f"(d[2]), "+f"(d[3])
        : "r"(a[0]), "r"(a[1]), "r"(a[2]), "r"(a[3]), "r"(b[0]), "r"(b[1]));
}
__device__ __forceinline__ void cp_async16(uint32_t dst, const void* src) {
    asm volatile("cp.async.cg.shared.global [%0], [%1], 16;" :: "r"(dst), "l"(src));
}
#define CP_COMMIT() asm volatile("cp.async.commit_group;" ::: "memory")
#define CP_WAIT0()  asm volatile("cp.async.wait_group 0;" ::: "memory")

// ---------------------------------------------------------------------------
// Tiled transpose + bf16 convert: out[n][k] = bf16(in[k][n]).
// ---------------------------------------------------------------------------
__global__ __launch_bounds__(256) void prep_weights(
    const float* __restrict__ aw1, const float* __restrict__ aw2,
    const float* __restrict__ lw1, const float* __restrict__ lw2)
{
    __shared__ float ts[32][33];
    int bid = blockIdx.x;
    const float* in;
    __nv_bfloat16* out;
    int rows, cols, t;
    if (bid < 8)        { in = aw1; out = g_aw1t; rows = 64;  cols = 128; t = bid; }
    else if (bid < 24)  { in = aw2; out = g_aw2t; rows = 128; cols = 128; t = bid - 8; }
    else if (bid < 56)  { in = lw1; out = g_lw1t; rows = 256; cols = 128; t = bid - 24; }
    else                { in = lw2; out = g_lw2t; rows = 128; cols = 128; t = bid - 56; }

    int tilesPerRow = cols / 32;
    int r0 = (t / tilesPerRow) * 32;
    int c0 = (t % tilesPerRow) * 32;
    int tx = threadIdx.x & 31, ty = threadIdx.x >> 5;

#pragma unroll
    for (int i = 0; i < 4; i++)
        ts[ty + i * 8][tx] = in[(size_t)(r0 + ty + i * 8) * cols + c0 + tx];
    __syncthreads();
#pragma unroll
    for (int i = 0; i < 4; i++) {
        int n = ty + i * 8;
        out[(size_t)(c0 + n) * rows + r0 + tx] = __float2bfloat16(ts[tx][n]);
    }
}

// ---------------------------------------------------------------------------
// Persistent fused MLP (Round-8 proven). Fixed smem layout (sized for KIN=256):
//   [0,      67584)  W1T  [128][264] bf16
//   [67584, 102400)  W2T  [128][136] bf16
//   [102400,136192)  r_x  X tile [64][264] bf16
//   [136192,153600)  r_h  hidden / out-stage [64][136] bf16
//   [153600,154624)  biases (2x128 fp32)
// ---------------------------------------------------------------------------
#define OFF_W2 67584
#define OFF_RX 102400
#define OFF_RH 136192
#define OFF_B  153600
#define SMEM_TOTAL 154624

template <int KIN>
__device__ void persist_phase(
    const float* __restrict__ X0, const float* __restrict__ X1, int split, int nTiles,
    const __nv_bfloat16* __restrict__ w1t, const __nv_bfloat16* __restrict__ w2t,
    const float* __restrict__ b1g, const float* __restrict__ b2g,
    __nv_bfloat16* __restrict__ out0, __nv_bfloat16* __restrict__ out1, char* smem)
{
    constexpr int S1 = KIN + 8;
    constexpr int SH = H_ + 8;
    constexpr int XV = 64 * KIN / 4 / 256;      // float4 per thread per X tile

    char* rw1 = smem;
    char* rw2 = smem + OFF_W2;
    char* rx  = smem + OFF_RX;
    char* rh  = smem + OFF_RH;
    float* b1s = (float*)(smem + OFF_B);
    float* b2s = b1s + 128;
    const uint32_t sw1 = smem_u32(rw1);
    const uint32_t sw2 = smem_u32(rw2);
    const uint32_t sx  = smem_u32(rx);
    const uint32_t sh  = smem_u32(rh);

    const int tid  = threadIdx.x;
    const int wid  = tid >> 5;
    const int lane = tid & 31;
    const int wr0 = (wid >> 2) * 32;
    const int wc0 = (wid & 3) * 32;
    const int a_row = (lane & 7) + ((lane >> 3) & 1) * 8;
    const int a_k   = (lane >> 4) * 8;
    const int b_n   = (lane & 7) + ((lane >> 4) & 1) * 8;
    const int b_k   = ((lane >> 3) & 1) * 8;
    const int tr = lane >> 2, tc = (lane & 3) * 2;

    // ---- prologue: stage weights (once) + first X tile ----
    if (tid < 128) { b1s[tid] = b1g[tid]; b2s[tid] = b2g[tid]; }
    {
        constexpr int NC = 128 * KIN / 8 / 256;
#pragma unroll
        for (int p = 0; p < NC; p++) {
            int idx = tid + p * 256;
            int r = idx / (KIN / 8), c = (idx % (KIN / 8)) * 8;
            cp_async16(sw1 + (uint32_t)(r * S1 + c) * 2, w1t + r * KIN + c);
        }
#pragma unroll
        for (int p = 0; p < 8; p++) {
            int idx = tid + p * 256;
            int r = idx >> 4, c = (idx & 15) * 8;
            cp_async16(sw2 + (uint32_t)(r * SH + c) * 2, w2t + r * H_ + c);
        }
        CP_COMMIT();
    }
    {
        int t0 = blockIdx.x;
        if (t0 < nTiles) {
            const float* Xp = (t0 < split) ? X0 + (size_t)t0 * 64 * KIN
                                           : X1 + (size_t)(t0 - split) * 64 * KIN;
#pragma unroll
            for (int p = 0; p < XV; p++) {
                int idx = tid + p * 256;
                int r = idx / (KIN / 4), c = (idx % (KIN / 4)) * 4;
                float4 v = *(const float4*)(Xp + (size_t)r * KIN + c);
                uint2 u;
                u.x = pack_bf16x2(san(v.x), san(v.y));
                u.y = pack_bf16x2(san(v.z), san(v.w));
                *(uint2*)(rx + (r * S1 + c) * 2) = u;
            }
        }
    }
    CP_WAIT0();
    __syncthreads();

    // ---- persistent tile loop ----
    for (int t = blockIdx.x; t < nTiles; t += PGRID) {
        __nv_bfloat16* out = (t < split) ? out0 + (size_t)t * 64 * H_
                                         : out1 + (size_t)(t - split) * 64 * H_;
        int nt = t + PGRID;
        bool hn = nt < nTiles;

        // prefetch next X into regs (hidden behind mma1)
        float4 xr[XV];
        if (hn) {
            const float* Xn = (nt < split) ? X0 + (size_t)nt * 64 * KIN
                                           : X1 + (size_t)(nt - split) * 64 * KIN;
#pragma unroll
            for (int p = 0; p < XV; p++) {
                int idx = tid + p * 256;
                int r = idx / (KIN / 4), c = (idx % (KIN / 4)) * 4;
                xr[p] = *(const float4*)(Xn + (size_t)r * KIN + c);
            }
        }

        float acc[2][4][4];
#pragma unroll
        for (int mi = 0; mi < 2; mi++)
#pragma unroll
            for (int ni = 0; ni < 4; ni++)
#pragma unroll
                for (int q = 0; q < 4; q++) acc[mi][ni][q] = 0.0f;

        // ---- layer 1 mma: A = rx, B = rw1 ----
        {
            uint32_t aaddr[2], baddr[2];
#pragma unroll
            for (int mi = 0; mi < 2; mi++)
                aaddr[mi] = sx + (uint32_t)((wr0 + mi * 16 + a_row) * S1 + a_k) * 2;
#pragma unroll
            for (int bi = 0; bi < 2; bi++)
                baddr[bi] = sw1 + (uint32_t)((wc0 + bi * 16 + b_n) * S1 + b_k) * 2;
#pragma unroll
            for (int ks = 0; ks < KIN / 16; ks++) {
                uint32_t a[2][4], b[4][2];
#pragma unroll
                for (int mi = 0; mi < 2; mi++) ldsm4(a[mi], aaddr[mi] + ks * 32);
#pragma unroll
                for (int bi = 0; bi < 2; bi++) {
                    uint32_t tq[4];
                    ldsm4(tq, baddr[bi] + ks * 32);
                    b[bi * 2][0] = tq[0]; b[bi * 2][1] = tq[1];
                    b[bi * 2 + 1][0] = tq[2]; b[bi * 2 + 1][1] = tq[3];
                }
#pragma unroll
                for (int mi = 0; mi < 2; mi++)
#pragma unroll
                    for (int ni = 0; ni < 4; ni++) mma16816(acc[mi][ni], a[mi], b[ni]);
            }
        }
        __syncthreads();   // S1: rx consumed

        // ---- epilogue 1: hidden -> rh ; store next X -> rx ----
#pragma unroll
        for (int mi = 0; mi < 2; mi++)
#pragma unroll
            for (int ni = 0; ni < 4; ni++) {
                int col = wc0 + ni * 8 + tc;
                float bb0 = b1s[col], bb1 = b1s[col + 1];
                int row0 = wr0 + mi * 16 + tr;
                *(uint32_t*)(rh + (row0 * SH + col) * 2) =
                    pack_bf16x2(fmaxf(acc[mi][ni][0] + bb0, 0.0f),
                                fmaxf(acc[mi][ni][1] + bb1, 0.0f));
                *(uint32_t*)(rh + ((row0 + 8) * SH + col) * 2) =
                    pack_bf16x2(fmaxf(acc[mi][ni][2] + bb0, 0.0f),
                                fmaxf(acc[mi][ni][3] + bb1, 0.0f));
            }
        if (hn) {
#pragma unroll
            for (int p = 0; p < XV; p++) {
                int idx = tid + p * 256;
                int r = idx / (KIN / 4), c = (idx % (KIN / 4)) * 4;
                uint2 u;
                u.x = pack_bf16x2(san(xr[p].x), san(xr[p].y));
                u.y = pack_bf16x2(san(xr[p].z), san(xr[p].w));
                *(uint2*)(rx + (r * S1 + c) * 2) = u;
            }
        }
        __syncthreads();   // S2: rh ready, rx ready for next iter

        // ---- layer 2 mma: A = rh, B = rw2 ----
#pragma unroll
        for (int mi = 0; mi < 2; mi++)
#pragma unroll
            for (int ni = 0; ni < 4; ni++)
#pragma unroll
                for (int q = 0; q < 4; q++) acc[mi][ni][q] = 0.0f;
        {
            uint32_t aaddr[2], baddr[2];
#pragma unroll
            for (int mi = 0; mi < 2; mi++)
                aaddr[mi] = sh + (uint32_t)((wr0 + mi * 16 + a_row) * SH + a_k) * 2;
#pragma unroll
            for (int bi = 0; bi < 2; bi++)
                baddr[bi] = sw2 + (uint32_t)((wc0 + bi * 16 + b_n) * SH + b_k) * 2;
#pragma unroll
            for (int ks = 0; ks < H_ / 16; ks++) {
                uint32_t a[2][4], b[4][2];
#pragma unroll
                for (int mi = 0; mi < 2; mi++) ldsm4(a[mi], aaddr[mi] + ks * 32);
#pragma unroll
                for (int bi = 0; bi < 2; bi++) {
                    uint32_t tq[4];
                    ldsm4(tq, baddr[bi] + ks * 32);
                    b[bi * 2][0] = tq[0]; b[bi * 2][1] = tq[1];
                    b[bi * 2 + 1][0] = tq[2]; b[bi * 2 + 1][1] = tq[3];
                }
#pragma unroll
                for (int mi = 0; mi < 2; mi++)
#pragma unroll
                    for (int ni = 0; ni < 4; ni++) mma16816(acc[mi][ni], a[mi], b[ni]);
            }
        }
        __syncthreads();   // S3: rh consumed

        // ---- epilogue 2: out-stage -> rh ----
#pragma unroll
        for (int mi = 0; mi < 2; mi++)
#pragma unroll
            for (int ni = 0; ni < 4; ni++) {
                int col = wc0 + ni * 8 + tc;
                float bb0 = b2s[col], bb1 = b2s[col + 1];
                int row0 = wr0 + mi * 16 + tr;
                *(uint32_t*)(rh + (row0 * SH + col) * 2) =
                    pack_bf16x2(san(acc[mi][ni][0] + bb0), san(acc[mi][ni][1] + bb1));
                *(uint32_t*)(rh + ((row0 + 8) * SH + col) * 2) =
                    pack_bf16x2(san(acc[mi][ni][2] + bb0), san(acc[mi][ni][3] + bb1));
            }
        __syncthreads();   // S4: rh staged

        // ---- coalesced store ----
        {
            uint4* dst = (uint4*)out;
            const uint4* src = (const uint4*)rh;
            for (int i = tid; i < 1024; i += 256) {
                int r = i >> 4, c = i & 15;
                dst[i] = src[r * (SH / 8) + c];
            }
        }
        // next iter's epi1 write to rh is fenced by next S1
    }
}

__global__ __launch_bounds__(256, 1) void persist_mlp(
    const float* __restrict__ action, const float* __restrict__ latent,
    const float* __restrict__ queue,
    const float* __restrict__ ab1, const float* __restrict__ ab2,
    const float* __restrict__ lb1, const float* __restrict__ lb2)
{
    extern __shared__ __align__(16) char smem[];
    // phase 1: queue (1024 tiles) + latent (256 tiles), KIN=256
    persist_phase<LATENT_>(queue, latent, 1024, 1280, g_lw1t, g_lw2t, lb1, lb2,
                           g_negemb, g_emb_l, smem);
    __syncthreads();
    // phase 2: action (256 tiles), KIN=64
    persist_phase<ACT_>(action, action, 256, 256, g_aw1t, g_aw2t, ab1, ab2,
                        g_emb_a, g_emb_a, smem);
}

// ---------------------------------------------------------------------------
// Loss: one warp per sample. Each half-warp processes one negative per step
// (16 lanes x 16B = full 256B row, coalesced). 16 steps, 4-shfl butterfly
// within the half; logits land one-per-lane in a permuted order (harmless:
// softmax reductions are symmetric).
// ---------------------------------------------------------------------------
__device__ __forceinline__ float2 bf2(uint32_t u) {
    return __bfloat1622float2(*reinterpret_cast<__nv_bfloat162*>(&u));
}
__device__ __forceinline__ float dot8(uint4 a, uint4 n) {
    float2 a0 = bf2(a.x), a1 = bf2(a.y), a2 = bf2(a.z), a3 = bf2(a.w);
    float2 n0 = bf2(n.x), n1 = bf2(n.y), n2 = bf2(n.z), n3 = bf2(n.w);
    float s = a0.x * n0.x + a0.y * n0.y;
    s += a1.x * n1.x + a1.y * n1.y;
    s += a2.x * n2.x + a2.y * n2.y;
    s += a3.x * n3.x + a3.y * n3.y;
    return s;
}

__global__ __launch_bounds__(256) void loss_kernel(
    const int* __restrict__ neg_idx,
    const float* __restrict__ temp_ptr,
    float* __restrict__ out)
{
    const int warp = threadIdx.x >> 5;
    const int lane = threadIdx.x & 31;
    const int lh   = lane & 15;                 // lane within half-warp
    const int halfBase = lane & 16;             // 0 or 16
    const int b = blockIdx.x * 8 + warp;

    float t = *temp_ptr;
    if (!isfinite(t)) t = 0.1f;
    t = fminf(fmaxf(t, 0.01f), 10.0f);
    const float invt = 1.0f / t;

    // emb_a chunk for the half-warp dot: 16B covering dims lh*8 .. lh*8+7
    const uint4 av = *(const uint4*)(g_emb_a + (size_t)b * H_ + lh * 8);
    const int my_idx = neg_idx[b * K_ + lane];

    // ---- 32 negative logits: 16 steps, 2 rows per step ----
    float myneg = 0.0f;
#pragma unroll
    for (int j = 0; j < 16; j++) {
        int row = __shfl_sync(0xffffffffu, my_idx, halfBase + j);
        uint4 nv = *(const uint4*)(g_negemb + (size_t)row * H_ + lh * 8);
        float d = dot8(av, nv);
        d += __shfl_xor_sync(0xffffffffu, d, 1);
        d += __shfl_xor_sync(0xffffffffu, d, 2);
        d += __shfl_xor_sync(0xffffffffu, d, 4);
        d += __shfl_xor_sync(0xffffffffu, d, 8);
        if (lh == j) myneg = d;
    }

    // ---- positive logit ----
    uint2 au = *(const uint2*)(g_emb_a + (size_t)b * H_ + lane * 4);
    uint2 lu = *(const uint2*)(g_emb_l + (size_t)b * H_ + lane * 4);
    float2 a01 = bf2(au.x), a23 = bf2(au.y);
    float2 l01 = bf2(lu.x), l23 = bf2(lu.y);
    float s = a01.x * l01.x + a01.y * l01.y + a23.x * l23.x + a23.y * l23.y;
#pragma unroll
    for (int o = 16; o > 0; o >>= 1) s += __shfl_xor_sync(0xffffffffu, s, o);
    float pos = s;

    pos *= invt;
    if (!isfinite(pos)) pos = 0.0f;
    pos = fminf(fmaxf(pos, -20.0f), 20.0f);
    myneg *= invt;
    if (!isfinite(myneg)) myneg = 0.0f;
    myneg = fminf(fmaxf(myneg, -20.0f), 20.0f);

    // ---- log-softmax over 33 logits (one negative per lane + pos) ----
    float m = myneg;
#pragma unroll
    for (int o = 16; o > 0; o >>= 1) m = fmaxf(m, __shfl_xor_sync(0xffffffffu, m, o));
    m = fmaxf(m, pos);

    float se = expf(myneg - m);
    float sl = myneg;
#pragma unroll
    for (int o = 16; o > 0; o >>= 1) {
        se += __shfl_xor_sync(0xffffffffu, se, o);
        sl += __shfl_xor_sync(0xffffffffu, sl, o);
    }
    se += expf(pos - m);
    sl += pos;

    float lse = m + logf(se);
    float logp0 = pos - lse;
    float meanlogp = sl * (1.0f / 33.0f) - lse;

    float loss = -(1.0f - EPS_) * logp0 - EPS_ * meanlogp;
    if (!isfinite(loss)) loss = 0.0f;
    loss = fminf(fmaxf(loss, -10.0f), 10.0f);

    if (lane == 0) out[b] = -loss;
}

// ---------------------------------------------------------------------------
extern "C" void kernel_launch(void* const* d_in, const int* in_sizes, int n_in,
                              void* d_out, int out_size)
{
    const float* action  = (const float*)d_in[0];
    const float* latent  = (const float*)d_in[1];
    const float* queue   = (const float*)d_in[2];
    const int*   neg_idx = (const int*)  d_in[3];
    const float* a_w1 = (const float*)d_in[4];
    const float* a_b1 = (const float*)d_in[5];
    const float* a_w2 = (const float*)d_in[6];
    const float* a_b2 = (const float*)d_in[7];
    const float* l_w1 = (const float*)d_in[8];
    const float* l_b1 = (const float*)d_in[9];
    const float* l_w2 = (const float*)d_in[10];
    const float* l_b2 = (const float*)d_in[11];
    const float* temp = (const float*)d_in[12];
    float* out = (float*)d_out;

    cudaFuncSetAttribute((const void*)persist_mlp,
                         cudaFuncAttributeMaxDynamicSharedMemorySize, SMEM_TOTAL);

    prep_weights<<<72, 256>>>(a_w1, a_w2, l_w1, l_w2);

    persist_mlp<<<PGRID, 256, SMEM_TOTAL>>>(action, latent, queue,
                                            a_b1, a_b2, l_b1, l_b2);

    loss_kernel<<<B_ / 8, 256>>>(neg_idx, temp, out);
}